// round 13
// baseline (speedup 1.0000x reference)
#include <cuda_runtime.h>
#include <cuda_bf16.h>
#include <cuda_fp16.h>
#include <cuda_fp8.h>
#include <cstdint>

#define DI __device__ __forceinline__

static constexpr int GROUPS = 8, MTOK = 2048, HID = 1024, INTER = 4096;

// ---------------------------------------------------------------------------
// Split-plane layout: logical fp32 matrix [R, K] stored as rows of consecutive
// 32-k blocks of 128 bytes: [32 x fp16 hi | 32 x e4m3 hi*2^e | 32 x e4m3 lo*2^(e+11)].
// Row r occupies (K/32)*128 bytes contiguously. 128B rows -> SW128 swizzle in
// SMEM, conflict-free for cp.async 16B chunks and ldmatrix.
//   D = Ah(f16)*Bh(f16)  +  2^-(eA+eB+11) * [ Ah8*Bl8 + Al8*Bh8 ]  (e4m3 k32 mma)
// ---------------------------------------------------------------------------

__device__ __nv_bfloat16 g_x [(size_t)GROUPS * MTOK * HID * 2];
__device__ __nv_bfloat16 g_w1[(size_t)GROUPS * INTER * HID * 2];
__device__ __nv_bfloat16 g_w2[(size_t)GROUPS * HID * INTER * 2];
__device__ __nv_bfloat16 g_h1[(size_t)GROUPS * MTOK * INTER * 2];

// ------------------------------ helpers ------------------------------------
DI uint32_t smem_u32(const void* p) {
    uint32_t a;
    asm("{ .reg .u64 t; cvta.to.shared.u64 t, %1; cvt.u32.u64 %0, t; }" : "=r"(a) : "l"(p));
    return a;
}
DI uint32_t swz(uint32_t off) { return off ^ ((off >> 3) & 0x70); }

DI void cp16(uint32_t s, const void* g) {
    asm volatile("cp.async.cg.shared.global [%0], [%1], 16;"
                 :: "r"(s), "l"(__cvta_generic_to_global(g)) : "memory");
}
DI void cp_commit() { asm volatile("cp.async.commit_group;" ::: "memory"); }

DI void ldm4(uint32_t* r, uint32_t addr) {
    asm volatile("ldmatrix.sync.aligned.m8n8.x4.shared.b16 {%0,%1,%2,%3}, [%4];"
                 : "=r"(r[0]), "=r"(r[1]), "=r"(r[2]), "=r"(r[3]) : "r"(addr));
}
DI void ldm2(uint32_t* r, uint32_t addr) {
    asm volatile("ldmatrix.sync.aligned.m8n8.x2.shared.b16 {%0,%1}, [%2];"
                 : "=r"(r[0]), "=r"(r[1]) : "r"(addr));
}
DI void mma_f16(float* d, const uint32_t* a, const uint32_t* b) {
    asm volatile(
        "mma.sync.aligned.m16n8k16.row.col.f32.f16.f16.f32 "
        "{%0,%1,%2,%3}, {%4,%5,%6,%7}, {%8,%9}, {%0,%1,%2,%3};"
        : "+f"(d[0]), "+f"(d[1]), "+f"(d[2]), "+f"(d[3])
        : "r"(a[0]), "r"(a[1]), "r"(a[2]), "r"(a[3]), "r"(b[0]), "r"(b[1]));
}
DI void mma_fp8(float* d, const uint32_t* a, const uint32_t* b) {
    asm volatile(
        "mma.sync.aligned.m16n8k32.row.col.f32.e4m3.e4m3.f32 "
        "{%0,%1,%2,%3}, {%4,%5,%6,%7}, {%8,%9}, {%0,%1,%2,%3};"
        : "+f"(d[0]), "+f"(d[1]), "+f"(d[2]), "+f"(d[3])
        : "r"(a[0]), "r"(a[1]), "r"(a[2]), "r"(a[3]), "r"(b[0]), "r"(b[1]));
}

DI uint16_t cvt_fp8x2(float a, float b) {
    return (uint16_t)__nv_cvt_float2_to_fp8x2(make_float2(a, b), __NV_SATFINITE, __NV_E4M3);
}

// ------------------------------ split prep ---------------------------------
// Convert fp32 [R, K] into the fp16/fp8 block layout. One float4 per thread.
// sHi = 2^e (per-matrix exponent centering for e4m3), lo plane scaled 2^(e+11).
template <int T>  // 0 -> x, 1 -> W1, 2 -> W2
__global__ void split_kernel(const float4* __restrict__ src, int n4, int K, float sHi) {
    char* dst = reinterpret_cast<char*>((T == 0) ? g_x : ((T == 1) ? g_w1 : g_w2));
    int i = blockIdx.x * 256 + threadIdx.x;
    if (i >= n4) return;
    float4 v = src[i];
    __half2 h01 = __float22half2_rn(make_float2(v.x, v.y));
    __half2 h23 = __float22half2_rn(make_float2(v.z, v.w));
    float l0 = v.x - __half2float(__low2half(h01));
    float l1 = v.y - __half2float(__high2half(h01));
    float l2 = v.z - __half2float(__low2half(h23));
    float l3 = v.w - __half2float(__high2half(h23));
    const float sLo = sHi * 2048.0f;
    uint32_t hi8 = (uint32_t)cvt_fp8x2(v.x * sHi, v.y * sHi)
                 | ((uint32_t)cvt_fp8x2(v.z * sHi, v.w * sHi) << 16);
    uint32_t lo8 = (uint32_t)cvt_fp8x2(l0 * sLo, l1 * sLo)
                 | ((uint32_t)cvt_fp8x2(l2 * sLo, l3 * sLo) << 16);
    int f0 = i * 4;
    int r = f0 / K, k = f0 % K;
    int kb = k >> 5, ko = k & 31;
    char* row = dst + ((size_t)r * (K >> 5) + kb) * 128;
    *reinterpret_cast<uint2*>(row + 2 * ko) =
        make_uint2(*reinterpret_cast<uint32_t*>(&h01), *reinterpret_cast<uint32_t*>(&h23));
    *reinterpret_cast<uint32_t*>(row + 64 + ko) = hi8;
    *reinterpret_cast<uint32_t*>(row + 96 + ko) = lo8;
}

// ------------------------------ GEMM kernel ---------------------------------
// CTA tile 128(M) x 128(N), BK = 32 k per stage. Stage smem: A 16KB + B 16KB.
// 6 stages = 192KB. 8 warps: wm = w&1 (M), wn = w>>1 (N). Warp tile 64x32.
// MODE 0: h1 = x @ W1^T + b1 -> split-layout g_h1 (CSCALE 2^-16)
// MODE 1: out = h1 @ W2^T + b2 -> fp32 d_out      (CSCALE 2^-17)
static constexpr int NSTAGE = 6;
static constexpr uint32_t STG_BYTES = 32768;
static constexpr uint32_t SMEM_DYN = NSTAGE * STG_BYTES;

template <int MODE>
__global__ __launch_bounds__(256, 1) void gemm_kernel(const float* __restrict__ bias,
                                                      float* __restrict__ outp) {
    constexpr int K = (MODE == 0) ? HID : INTER;
    constexpr int N = (MODE == 0) ? INTER : HID;
    constexpr int NST = K / 32;
    constexpr long STRIDE = (long)(K / 32) * 128;  // bytes per row (A and B)
    const float CSCALE = (MODE == 0) ? 0x1p-16f : 0x1p-17f;

    const int gB = blockIdx.z;
    const int mbase = blockIdx.y * 128;
    const int nbase = blockIdx.x * 128;
    const int t = threadIdx.x;
    const int lane = t & 31, w = t >> 5;
    const int wm = w & 1, wn = w >> 1;

    const char* Abase = reinterpret_cast<const char*>((MODE == 0) ? g_x : g_h1)
                      + ((size_t)gB * MTOK + mbase) * STRIDE;
    const char* Bbase = reinterpret_cast<const char*>((MODE == 0) ? g_w1 : g_w2)
                      + ((size_t)gB * N + nbase) * STRIDE;

    extern __shared__ char smem[];
    const uint32_t sb = smem_u32(smem);

    // fp16 ldmatrix lane offsets (16 rows x 16 b16-cols tiles)
    const int rowA = (lane & 7) + ((lane >> 3) & 1) * 8;
    const int kA   = (lane >> 4) * 8;
    const int rowB = (lane & 7) + ((lane >> 4) & 1) * 8;
    const int kB   = ((lane >> 3) & 1) * 8;
    const uint32_t offA16 = (uint32_t)((wm * 64 + rowA) * 128 + kA * 2);
    const uint32_t offB16 = (uint32_t)((wn * 32 + rowB) * 128 + kB * 2);
    // fp8 A ldmatrix lane offsets (16 rows x 32 bytes, 4 b16 tiles)
    const uint32_t offA8 = (uint32_t)((wm * 64 + (lane & 7) + ((lane >> 3) & 1) * 8) * 128
                                      + 64 + ((lane >> 4) & 1) * 16);
    // fp8 B ldmatrix lane offsets (8 rows x 32 bytes, 2 b16 tiles)
    const uint32_t offB8 = (uint32_t)((wn * 32 + (lane & 7)) * 128
                                      + 64 + ((lane >> 3) & 1) * 16);

    float dh[4][4][4], dc[4][4][4];
    #pragma unroll
    for (int a = 0; a < 4; a++)
        #pragma unroll
        for (int b = 0; b < 4; b++)
            #pragma unroll
            for (int c = 0; c < 4; c++) { dh[a][b][c] = 0.f; dc[a][b][c] = 0.f; }

    auto load_stage = [&](int s) {
        const uint32_t dst = sb + (uint32_t)(s % NSTAGE) * STG_BYTES;
        const char* As = Abase + (size_t)s * 128;
        const char* Bs = Bbase + (size_t)s * 128;
        #pragma unroll
        for (int i = 0; i < 4; i++) {
            int q = t + 256 * i;
            int row = q >> 3, cb = (q & 7) * 16;
            uint32_t so = swz((uint32_t)(row * 128 + cb));
            cp16(dst + so,         As + (size_t)row * STRIDE + cb);
            cp16(dst + 16384 + so, Bs + (size_t)row * STRIDE + cb);
        }
        cp_commit();
    };

    #pragma unroll
    for (int s = 0; s < NSTAGE - 1; s++) load_stage(s);

    for (int ks = 0; ks < NST; ks++) {
        asm volatile("cp.async.wait_group 4;" ::: "memory");
        __syncthreads();
        if (ks + NSTAGE - 1 < NST) load_stage(ks + NSTAGE - 1);
        else cp_commit();

        const uint32_t ab = sb + (uint32_t)(ks % NSTAGE) * STG_BYTES;
        const uint32_t bb = ab + 16384;

        // ---- fp16 hi * hi ----
        #pragma unroll
        for (int ki = 0; ki < 2; ki++) {
            uint32_t ah[4][4], bh[2][4];
            #pragma unroll
            for (int mt = 0; mt < 4; mt++)
                ldm4(ah[mt], ab + swz(offA16 + (uint32_t)(mt * 2048 + ki * 32)));
            #pragma unroll
            for (int np = 0; np < 2; np++)
                ldm4(bh[np], bb + swz(offB16 + (uint32_t)(np * 2048 + ki * 32)));
            #pragma unroll
            for (int mt = 0; mt < 4; mt++)
                #pragma unroll
                for (int nt = 0; nt < 4; nt++)
                    mma_f16(dh[mt][nt], ah[mt], &bh[nt >> 1][(nt & 1) * 2]);
        }

        // ---- fp8 cross terms: Ah8*Bl8 + Al8*Bh8 (k=32 per mma) ----
        {
            uint32_t a8h[4][4], a8l[4][4], b8h[4][2], b8l[4][2];
            #pragma unroll
            for (int mt = 0; mt < 4; mt++) {
                ldm4(a8h[mt], ab + swz(offA8 + (uint32_t)(mt * 2048)));
                ldm4(a8l[mt], ab + swz(offA8 + (uint32_t)(mt * 2048) + 32));
            }
            #pragma unroll
            for (int nt = 0; nt < 4; nt++) {
                ldm2(b8h[nt], bb + swz(offB8 + (uint32_t)(nt * 1024)));
                ldm2(b8l[nt], bb + swz(offB8 + (uint32_t)(nt * 1024) + 32));
            }
            #pragma unroll
            for (int mt = 0; mt < 4; mt++)
                #pragma unroll
                for (int nt = 0; nt < 4; nt++) {
                    mma_fp8(dc[mt][nt], a8h[mt], b8l[nt]);
                    mma_fp8(dc[mt][nt], a8l[mt], b8h[nt]);
                }
        }
    }

    // ------------------------------ epilogue --------------------------------
    const int g = lane >> 2, tg = lane & 3;
    const float* bs = bias + (size_t)gB * N;
    #pragma unroll
    for (int mt = 0; mt < 4; mt++) {
        #pragma unroll
        for (int half = 0; half < 2; half++) {
            const int mrow = mbase + wm * 64 + mt * 16 + g + half * 8;
            #pragma unroll
            for (int nt = 0; nt < 4; nt++) {
                const int col = nbase + wn * 32 + nt * 8 + 2 * tg;
                float v0 = dh[mt][nt][half * 2 + 0] + dc[mt][nt][half * 2 + 0] * CSCALE + bs[col];
                float v1 = dh[mt][nt][half * 2 + 1] + dc[mt][nt][half * 2 + 1] * CSCALE + bs[col + 1];
                if (MODE == 0) {
                    __half2 h2 = __float22half2_rn(make_float2(v0, v1));
                    float l0 = v0 - __half2float(__low2half(h2));
                    float l1 = v1 - __half2float(__high2half(h2));
                    uint16_t hi8 = cvt_fp8x2(v0, v1);
                    uint16_t lo8 = cvt_fp8x2(l0 * 2048.f, l1 * 2048.f);
                    char* row = reinterpret_cast<char*>(g_h1)
                              + ((size_t)(gB * MTOK + mrow) * (INTER >> 5) + (col >> 5)) * 128;
                    const int ko = col & 31;
                    *reinterpret_cast<uint32_t*>(row + 2 * ko) = *reinterpret_cast<uint32_t*>(&h2);
                    *reinterpret_cast<uint16_t*>(row + 64 + ko) = hi8;
                    *reinterpret_cast<uint16_t*>(row + 96 + ko) = lo8;
                } else {
                    *reinterpret_cast<float2*>(outp + ((size_t)gB * MTOK + mrow) * N + col) =
                        make_float2(v0, v1);
                }
            }
        }
    }
}

// ------------------------------ launch ---------------------------------
extern "C" void kernel_launch(void* const* d_in, const int* in_sizes, int n_in,
                              void* d_out, int out_size) {
    const float *x = nullptr, *W1 = nullptr, *b1 = nullptr, *W2 = nullptr, *b2 = nullptr;
    for (int i = 0; i < n_in; i++) {
        const int s = in_sizes[i];
        if (s == GROUPS * MTOK * HID)        x = (const float*)d_in[i];
        else if (s == GROUPS * INTER * HID) { if (!W1) W1 = (const float*)d_in[i];
                                              else      W2 = (const float*)d_in[i]; }
        else if (s == GROUPS * INTER)        b1 = (const float*)d_in[i];
        else if (s == GROUPS * HID)          b2 = (const float*)d_in[i];
    }

    cudaFuncSetAttribute(gemm_kernel<0>, cudaFuncAttributeMaxDynamicSharedMemorySize, SMEM_DYN);
    cudaFuncSetAttribute(gemm_kernel<1>, cudaFuncAttributeMaxDynamicSharedMemorySize, SMEM_DYN);

    // 1) split fp32 inputs into fp16/fp8 block layout
    {
        int n4x = GROUPS * MTOK * HID / 4;
        split_kernel<0><<<(n4x + 255) / 256, 256>>>((const float4*)x, n4x, HID, 1.0f);
        int n4w = GROUPS * INTER * HID / 4;
        split_kernel<1><<<(n4w + 255) / 256, 256>>>((const float4*)W1, n4w, HID, 32.0f);
        split_kernel<2><<<(n4w + 255) / 256, 256>>>((const float4*)W2, n4w, INTER, 64.0f);
    }

    // 2) GEMM1: h1 = x @ W1^T + b1  (M=2048, N=4096, K=1024 per group)
    {
        dim3 grid(INTER / 128, MTOK / 128, GROUPS);
        gemm_kernel<0><<<grid, 256, SMEM_DYN>>>(b1, nullptr);
    }

    // 3) GEMM2: out = h1 @ W2^T + b2 (M=2048, N=1024, K=4096 per group)
    {
        dim3 grid(HID / 128, MTOK / 128, GROUPS);
        gemm_kernel<1><<<grid, 256, SMEM_DYN>>>(b2, (float*)d_out);
    }
}

// round 14
// speedup vs baseline: 1.8703x; 1.8703x over previous
#include <cuda_runtime.h>
#include <cuda_fp16.h>
#include <cstdint>

#define DI __device__ __forceinline__

static constexpr int GROUPS = 8, MTOK = 2048, HID = 1024, INTER = 4096;

// ---------------------------------------------------------------------------
// 2-term fp16 scheme:  D = A * Bh + A * Bl,  out = D * 2^-s + bias
//   A (x / h1): plain row-major fp16.
//   B (W * 2^s, s=5 for W1, 6 for W2): per 32-k block of 128B:
//       [32 x fp16 hi | 32 x fp16 lo]   (lo = residual, normal-range)
// ---------------------------------------------------------------------------

__device__ __half g_x [(size_t)GROUPS * MTOK * HID];
__device__ __half g_w1[(size_t)GROUPS * INTER * HID * 2];
__device__ __half g_w2[(size_t)GROUPS * HID * INTER * 2];
__device__ __half g_h1[(size_t)GROUPS * MTOK * INTER];

// ------------------------------ helpers ------------------------------------
DI uint32_t smem_u32(const void* p) {
    uint32_t a;
    asm("{ .reg .u64 t; cvta.to.shared.u64 t, %1; cvt.u32.u64 %0, t; }" : "=r"(a) : "l"(p));
    return a;
}
DI uint32_t swz(uint32_t off) { return off ^ ((off >> 3) & 0x70); }

DI void cp16(uint32_t s, const void* g) {
    asm volatile("cp.async.cg.shared.global [%0], [%1], 16;"
                 :: "r"(s), "l"(__cvta_generic_to_global(g)) : "memory");
}
DI void cp_commit() { asm volatile("cp.async.commit_group;" ::: "memory"); }

DI void ldm4(uint32_t* r, uint32_t addr) {
    asm volatile("ldmatrix.sync.aligned.m8n8.x4.shared.b16 {%0,%1,%2,%3}, [%4];"
                 : "=r"(r[0]), "=r"(r[1]), "=r"(r[2]), "=r"(r[3]) : "r"(addr));
}
DI void mma_f16(float* d, const uint32_t* a, const uint32_t* b) {
    asm volatile(
        "mma.sync.aligned.m16n8k16.row.col.f32.f16.f16.f32 "
        "{%0,%1,%2,%3}, {%4,%5,%6,%7}, {%8,%9}, {%0,%1,%2,%3};"
        : "+f"(d[0]), "+f"(d[1]), "+f"(d[2]), "+f"(d[3])
        : "r"(a[0]), "r"(a[1]), "r"(a[2]), "r"(a[3]), "r"(b[0]), "r"(b[1]));
}

// ------------------------------ prep kernels --------------------------------
// x -> fp16 row-major (straight convert)
__global__ void conv_x_kernel(const float4* __restrict__ src, int n4) {
    int i = blockIdx.x * 256 + threadIdx.x;
    if (i >= n4) return;
    float4 v = src[i];
    __half2 h01 = __floats2half2_rn(v.x, v.y);
    __half2 h23 = __floats2half2_rn(v.z, v.w);
    *reinterpret_cast<uint2*>(g_x + (size_t)i * 4) =
        make_uint2(*reinterpret_cast<uint32_t*>(&h01), *reinterpret_cast<uint32_t*>(&h23));
}

// W -> scaled hi/lo fp16 block layout. One float4 (4 consecutive k) per thread.
template <int T>  // 1 -> W1 (K=HID, scale 32), 2 -> W2 (K=INTER, scale 64)
__global__ void split_w_kernel(const float4* __restrict__ src, int n4, int K, float sc) {
    char* dst = reinterpret_cast<char*>((T == 1) ? g_w1 : g_w2);
    int i = blockIdx.x * 256 + threadIdx.x;
    if (i >= n4) return;
    float4 v = src[i];
    float s0 = v.x * sc, s1 = v.y * sc, s2 = v.z * sc, s3 = v.w * sc;
    __half2 h01 = __floats2half2_rn(s0, s1);
    __half2 h23 = __floats2half2_rn(s2, s3);
    __half2 l01 = __floats2half2_rn(s0 - __half2float(__low2half(h01)),
                                    s1 - __half2float(__high2half(h01)));
    __half2 l23 = __floats2half2_rn(s2 - __half2float(__low2half(h23)),
                                    s3 - __half2float(__high2half(h23)));
    int f0 = i * 4;
    int r = f0 / K, k = f0 % K;
    int kb = k >> 5, ko = k & 31;
    char* row = dst + ((size_t)r * (K >> 5) + kb) * 128;
    *reinterpret_cast<uint2*>(row + 2 * ko) =
        make_uint2(*reinterpret_cast<uint32_t*>(&h01), *reinterpret_cast<uint32_t*>(&h23));
    *reinterpret_cast<uint2*>(row + 64 + 2 * ko) =
        make_uint2(*reinterpret_cast<uint32_t*>(&l01), *reinterpret_cast<uint32_t*>(&l23));
}

// ------------------------------ GEMM kernel ---------------------------------
// CTA tile 128(M) x 128(N), BK = 64 per stage.
// Stage smem: A 128x128B = 16KB @0;  B 2 blocks x (128 rows x 128B) = 32KB @16384.
// 4 stages x 48KB = 192KB. 8 warps: wm=w&1 (M), wn=w>>1 (N). Warp tile 64x32.
// MODE 0: h1 = x @ W1'^T * 2^-5 + b1 -> fp16 g_h1
// MODE 1: out = h1 @ W2'^T * 2^-6 + b2 -> fp32 d_out
static constexpr int NSTAGE = 4;
static constexpr uint32_t STG_BYTES = 49152;
static constexpr uint32_t SMEM_DYN = NSTAGE * STG_BYTES;  // 196608

template <int MODE>
__global__ __launch_bounds__(256, 1) void gemm_kernel(const float* __restrict__ bias,
                                                      float* __restrict__ outp) {
    constexpr int K = (MODE == 0) ? HID : INTER;
    constexpr int N = (MODE == 0) ? INTER : HID;
    constexpr int NST = K / 64;
    constexpr long STRIDE_A = (long)K * 2;   // bytes per A row (fp16)
    constexpr long STRIDE_B = (long)K * 4;   // bytes per B row (hi+lo planes)
    const float CSCALE = (MODE == 0) ? (1.0f / 32.0f) : (1.0f / 64.0f);

    const int gB = blockIdx.z;
    const int mbase = blockIdx.y * 128;
    const int nbase = blockIdx.x * 128;
    const int t = threadIdx.x;
    const int lane = t & 31, w = t >> 5;
    const int wm = w & 1, wn = w >> 1;

    const char* Abase = reinterpret_cast<const char*>((MODE == 0) ? g_x : g_h1)
                      + ((size_t)gB * MTOK + mbase) * STRIDE_A;
    const char* Bbase = reinterpret_cast<const char*>((MODE == 0) ? g_w1 : g_w2)
                      + ((size_t)gB * N + nbase) * STRIDE_B;

    extern __shared__ char smem[];
    const uint32_t sb = smem_u32(smem);

    // ldmatrix lane offsets (16x16 b16 tiles, x4)
    const int rowA = (lane & 7) + ((lane >> 3) & 1) * 8;
    const int kA   = (lane >> 4) * 8;                    // 0 or 8 (fp16 cols)
    const int rowB = (lane & 7) + ((lane >> 4) & 1) * 8;
    const int kB   = ((lane >> 3) & 1) * 8;
    const uint32_t offA = (uint32_t)((wm * 64 + rowA) * 128 + kA * 2);
    const uint32_t offB = (uint32_t)((wn * 32 + rowB) * 128 + kB * 2);

    float d[4][4][4];
    #pragma unroll
    for (int a = 0; a < 4; a++)
        #pragma unroll
        for (int b = 0; b < 4; b++)
            #pragma unroll
            for (int c = 0; c < 4; c++) d[a][b][c] = 0.f;

    auto load_stage = [&](int s) {
        const uint32_t dst = sb + (uint32_t)(s % NSTAGE) * STG_BYTES;
        // A: 128 rows x 128B (k = s*64 .. s*64+63), 1024 chunks, 4/thread
        const char* As = Abase + (size_t)s * 128;
        #pragma unroll
        for (int i = 0; i < 4; i++) {
            int q = t + 256 * i;
            int row = q >> 3, cb = (q & 7) * 16;
            cp16(dst + swz((uint32_t)(row * 128 + cb)), As + (size_t)row * STRIDE_A + cb);
        }
        // B: 2 k-blocks x 128 rows x 128B, 2048 chunks, 8/thread
        #pragma unroll
        for (int i = 0; i < 8; i++) {
            int q = t + 256 * i;
            int kb = q >> 10, r2 = q & 1023;
            int row = r2 >> 3, cb = (r2 & 7) * 16;
            const char* Bs = Bbase + (size_t)(s * 2 + kb) * 128;
            cp16(dst + 16384 + (uint32_t)kb * 16384 + swz((uint32_t)(row * 128 + cb)),
                 Bs + (size_t)row * STRIDE_B + cb);
        }
        cp_commit();
    };

    #pragma unroll
    for (int s = 0; s < NSTAGE - 1; s++) load_stage(s);

    for (int ks = 0; ks < NST; ks++) {
        asm volatile("cp.async.wait_group 2;" ::: "memory");
        __syncthreads();
        if (ks + NSTAGE - 1 < NST) load_stage(ks + NSTAGE - 1);
        else cp_commit();

        const uint32_t ab = sb + (uint32_t)(ks % NSTAGE) * STG_BYTES;

        #pragma unroll
        for (int kb = 0; kb < 2; kb++) {
            const uint32_t bb = ab + 16384 + (uint32_t)kb * 16384;
            #pragma unroll
            for (int ki = 0; ki < 2; ki++) {
                // A frags: 64 k per 128B row -> k16 step q = kb*2+ki at byte q*32
                uint32_t a4[4][4], bh[2][4], bl[2][4];
                const uint32_t akoff = (uint32_t)((kb * 2 + ki) * 32);
                #pragma unroll
                for (int mt = 0; mt < 4; mt++)
                    ldm4(a4[mt], ab + swz(offA + (uint32_t)(mt * 2048) + akoff));
                #pragma unroll
                for (int np = 0; np < 2; np++) {
                    const uint32_t bo = offB + (uint32_t)(np * 2048 + ki * 32);
                    ldm4(bh[np], bb + swz(bo));
                    ldm4(bl[np], bb + swz(bo + 64));
                }
                #pragma unroll
                for (int mt = 0; mt < 4; mt++)
                    #pragma unroll
                    for (int nt = 0; nt < 4; nt++) {
                        const int np = nt >> 1, sel = (nt & 1) * 2;
                        mma_f16(d[mt][nt], a4[mt], &bh[np][sel]);
                        mma_f16(d[mt][nt], a4[mt], &bl[np][sel]);
                    }
            }
        }
    }

    // ------------------------------ epilogue --------------------------------
    const int g = lane >> 2, tg = lane & 3;
    const float* bs = bias + (size_t)gB * N;
    #pragma unroll
    for (int mt = 0; mt < 4; mt++) {
        #pragma unroll
        for (int half = 0; half < 2; half++) {
            const int mrow = mbase + wm * 64 + mt * 16 + g + half * 8;
            #pragma unroll
            for (int nt = 0; nt < 4; nt++) {
                const int col = nbase + wn * 32 + nt * 8 + 2 * tg;
                float v0 = d[mt][nt][half * 2 + 0] * CSCALE + bs[col];
                float v1 = d[mt][nt][half * 2 + 1] * CSCALE + bs[col + 1];
                if (MODE == 0) {
                    __half2 h2 = __floats2half2_rn(v0, v1);
                    *reinterpret_cast<uint32_t*>(g_h1 + ((size_t)(gB * MTOK + mrow) * INTER + col)) =
                        *reinterpret_cast<uint32_t*>(&h2);
                } else {
                    *reinterpret_cast<float2*>(outp + ((size_t)gB * MTOK + mrow) * N + col) =
                        make_float2(v0, v1);
                }
            }
        }
    }
}

// ------------------------------ launch ---------------------------------
extern "C" void kernel_launch(void* const* d_in, const int* in_sizes, int n_in,
                              void* d_out, int out_size) {
    const float *x = nullptr, *W1 = nullptr, *b1 = nullptr, *W2 = nullptr, *b2 = nullptr;
    for (int i = 0; i < n_in; i++) {
        const int s = in_sizes[i];
        if (s == GROUPS * MTOK * HID)        x = (const float*)d_in[i];
        else if (s == GROUPS * INTER * HID) { if (!W1) W1 = (const float*)d_in[i];
                                              else      W2 = (const float*)d_in[i]; }
        else if (s == GROUPS * INTER)        b1 = (const float*)d_in[i];
        else if (s == GROUPS * HID)          b2 = (const float*)d_in[i];
    }

    cudaFuncSetAttribute(gemm_kernel<0>, cudaFuncAttributeMaxDynamicSharedMemorySize, SMEM_DYN);
    cudaFuncSetAttribute(gemm_kernel<1>, cudaFuncAttributeMaxDynamicSharedMemorySize, SMEM_DYN);

    // 1) prep: x -> fp16, W1/W2 -> scaled hi/lo split layout
    {
        int n4x = GROUPS * MTOK * HID / 4;
        conv_x_kernel<<<(n4x + 255) / 256, 256>>>((const float4*)x, n4x);
        int n4w = GROUPS * INTER * HID / 4;
        split_w_kernel<1><<<(n4w + 255) / 256, 256>>>((const float4*)W1, n4w, HID, 32.0f);
        split_w_kernel<2><<<(n4w + 255) / 256, 256>>>((const float4*)W2, n4w, INTER, 64.0f);
    }

    // 2) GEMM1: h1 = x @ W1^T + b1  (M=2048, N=4096, K=1024 per group)
    {
        dim3 grid(INTER / 128, MTOK / 128, GROUPS);
        gemm_kernel<0><<<grid, 256, SMEM_DYN>>>(b1, nullptr);
    }

    // 3) GEMM2: out = h1 @ W2^T + b2 (M=2048, N=1024, K=4096 per group)
    {
        dim3 grid(HID / 128, MTOK / 128, GROUPS);
        gemm_kernel<1><<<grid, 256, SMEM_DYN>>>(b2, (float*)d_out);
    }
}

// round 15
// speedup vs baseline: 3.1912x; 1.7062x over previous
#include <cuda_runtime.h>
#include <cuda_fp16.h>
#include <cstdint>

#define DI __device__ __forceinline__

static constexpr int GROUPS = 8, MTOK = 2048, HID = 1024, INTER = 4096;

// ---------------------------------------------------------------------------
// Single-term fp16 scheme: all operands plain row-major fp16, fp32 accumulate.
//   GEMM1: h1 = x @ W1^T + b1   (fp16 h1)
//   GEMM2: out = h1 @ W2^T + b2 (fp32 out)
// Calibrated error model: ~2.1e-4 per fp16-quant event, 4 events -> ~4.2e-4.
// ---------------------------------------------------------------------------

__device__ __half g_x [(size_t)GROUPS * MTOK * HID];
__device__ __half g_w1[(size_t)GROUPS * INTER * HID];
__device__ __half g_w2[(size_t)GROUPS * HID * INTER];
__device__ __half g_h1[(size_t)GROUPS * MTOK * INTER];

// ------------------------------ helpers ------------------------------------
DI uint32_t smem_u32(const void* p) {
    uint32_t a;
    asm("{ .reg .u64 t; cvta.to.shared.u64 t, %1; cvt.u32.u64 %0, t; }" : "=r"(a) : "l"(p));
    return a;
}
DI uint32_t swz(uint32_t off) { return off ^ ((off >> 3) & 0x70); }

DI void cp16(uint32_t s, const void* g) {
    asm volatile("cp.async.cg.shared.global [%0], [%1], 16;"
                 :: "r"(s), "l"(__cvta_generic_to_global(g)) : "memory");
}
DI void cp_commit() { asm volatile("cp.async.commit_group;" ::: "memory"); }

DI void ldm4(uint32_t* r, uint32_t addr) {
    asm volatile("ldmatrix.sync.aligned.m8n8.x4.shared.b16 {%0,%1,%2,%3}, [%4];"
                 : "=r"(r[0]), "=r"(r[1]), "=r"(r[2]), "=r"(r[3]) : "r"(addr));
}
DI void mma_f16(float* d, const uint32_t* a, const uint32_t* b) {
    asm volatile(
        "mma.sync.aligned.m16n8k16.row.col.f32.f16.f16.f32 "
        "{%0,%1,%2,%3}, {%4,%5,%6,%7}, {%8,%9}, {%0,%1,%2,%3};"
        : "+f"(d[0]), "+f"(d[1]), "+f"(d[2]), "+f"(d[3])
        : "r"(a[0]), "r"(a[1]), "r"(a[2]), "r"(a[3]), "r"(b[0]), "r"(b[1]));
}

// ------------------------------ prep kernel ---------------------------------
// fp32 -> fp16 row-major convert. T: 0 -> x, 1 -> W1, 2 -> W2.
template <int T>
__global__ void conv_kernel(const float4* __restrict__ src, int n4) {
    __half* dst = (T == 0) ? g_x : ((T == 1) ? g_w1 : g_w2);
    int i = blockIdx.x * 256 + threadIdx.x;
    if (i >= n4) return;
    float4 v = src[i];
    __half2 h01 = __floats2half2_rn(v.x, v.y);
    __half2 h23 = __floats2half2_rn(v.z, v.w);
    *reinterpret_cast<uint2*>(dst + (size_t)i * 4) =
        make_uint2(*reinterpret_cast<uint32_t*>(&h01), *reinterpret_cast<uint32_t*>(&h23));
}

// ------------------------------ GEMM kernel ---------------------------------
// CTA tile 128(M) x 256(N), BK = 64 per stage.
// Stage smem: A 128 rows x 128B = 16KB @0;  B 256 rows x 128B = 32KB @16384.
// 4 stages x 48KB = 192KB. 8 warps: wm = w&1 (M), wn = w>>1 (N). Warp tile 64x64.
// MODE 0: h1 = x @ W1^T + b1 -> fp16 g_h1
// MODE 1: out = h1 @ W2^T + b2 -> fp32 d_out
static constexpr int NSTAGE = 4;
static constexpr uint32_t STG_BYTES = 49152;
static constexpr uint32_t SMEM_DYN = NSTAGE * STG_BYTES;  // 196608

template <int MODE>
__global__ __launch_bounds__(256, 1) void gemm_kernel(const float* __restrict__ bias,
                                                      float* __restrict__ outp) {
    constexpr int K = (MODE == 0) ? HID : INTER;
    constexpr int N = (MODE == 0) ? INTER : HID;
    constexpr int NST = K / 64;
    constexpr long STRIDE = (long)K * 2;   // bytes per fp16 row (A and B)

    const int gB = blockIdx.z;
    const int mbase = blockIdx.y * 128;
    const int nbase = blockIdx.x * 256;
    const int t = threadIdx.x;
    const int lane = t & 31, w = t >> 5;
    const int wm = w & 1, wn = w >> 1;

    const char* Abase = reinterpret_cast<const char*>((MODE == 0) ? g_x : g_h1)
                      + ((size_t)gB * MTOK + mbase) * STRIDE;
    const char* Bbase = reinterpret_cast<const char*>((MODE == 0) ? g_w1 : g_w2)
                      + ((size_t)gB * N + nbase) * STRIDE;

    extern __shared__ char smem[];
    const uint32_t sb = smem_u32(smem);

    // ldmatrix lane offsets (16x16 b16 tiles, x4)
    const int rowA = (lane & 7) + ((lane >> 3) & 1) * 8;
    const int kA   = (lane >> 4) * 8;
    const int rowB = (lane & 7) + ((lane >> 4) & 1) * 8;
    const int kB   = ((lane >> 3) & 1) * 8;
    const uint32_t offA = (uint32_t)((wm * 64 + rowA) * 128 + kA * 2);
    const uint32_t offB = (uint32_t)((wn * 64 + rowB) * 128 + kB * 2);

    float d[4][8][4];
    #pragma unroll
    for (int a = 0; a < 4; a++)
        #pragma unroll
        for (int b = 0; b < 8; b++)
            #pragma unroll
            for (int c = 0; c < 4; c++) d[a][b][c] = 0.f;

    auto load_stage = [&](int s) {
        const uint32_t dst = sb + (uint32_t)(s % NSTAGE) * STG_BYTES;
        const char* As = Abase + (size_t)s * 128;   // k offset: s*64 fp16 = s*128 B
        #pragma unroll
        for (int i = 0; i < 4; i++) {               // A: 1024 chunks, 4/thread
            int q = t + 256 * i;
            int row = q >> 3, cb = (q & 7) * 16;
            cp16(dst + swz((uint32_t)(row * 128 + cb)), As + (size_t)row * STRIDE + cb);
        }
        const char* Bs = Bbase + (size_t)s * 128;
        #pragma unroll
        for (int i = 0; i < 8; i++) {               // B: 2048 chunks (256 rows), 8/thread
            int q = t + 256 * i;
            int row = q >> 3, cb = (q & 7) * 16;
            cp16(dst + 16384 + swz((uint32_t)(row * 128 + cb)), Bs + (size_t)row * STRIDE + cb);
        }
        cp_commit();
    };

    #pragma unroll
    for (int s = 0; s < NSTAGE - 1; s++) load_stage(s);

    for (int ks = 0; ks < NST; ks++) {
        asm volatile("cp.async.wait_group 2;" ::: "memory");
        __syncthreads();
        if (ks + NSTAGE - 1 < NST) load_stage(ks + NSTAGE - 1);
        else cp_commit();

        const uint32_t ab = sb + (uint32_t)(ks % NSTAGE) * STG_BYTES;
        const uint32_t bb = ab + 16384;

        #pragma unroll
        for (int ki = 0; ki < 4; ki++) {
            uint32_t a4[4][4], b4[4][4];
            const uint32_t ko = (uint32_t)(ki * 32);   // k16 step within 128B row
            #pragma unroll
            for (int mt = 0; mt < 4; mt++)
                ldm4(a4[mt], ab + swz(offA + (uint32_t)(mt * 2048) + ko));
            #pragma unroll
            for (int np = 0; np < 4; np++)
                ldm4(b4[np], bb + swz(offB + (uint32_t)(np * 2048) + ko));
            #pragma unroll
            for (int mt = 0; mt < 4; mt++)
                #pragma unroll
                for (int nt = 0; nt < 8; nt++)
                    mma_f16(d[mt][nt], a4[mt], &b4[nt >> 1][(nt & 1) * 2]);
        }
    }

    // ------------------------------ epilogue --------------------------------
    const int g = lane >> 2, tg = lane & 3;
    const float* bs = bias + (size_t)gB * N;
    float bc[8][2];
    #pragma unroll
    for (int nt = 0; nt < 8; nt++) {
        const int col = nbase + wn * 64 + nt * 8 + 2 * tg;
        bc[nt][0] = bs[col];
        bc[nt][1] = bs[col + 1];
    }
    #pragma unroll
    for (int mt = 0; mt < 4; mt++) {
        #pragma unroll
        for (int half = 0; half < 2; half++) {
            const int mrow = mbase + wm * 64 + mt * 16 + g + half * 8;
            #pragma unroll
            for (int nt = 0; nt < 8; nt++) {
                const int col = nbase + wn * 64 + nt * 8 + 2 * tg;
                float v0 = d[mt][nt][half * 2 + 0] + bc[nt][0];
                float v1 = d[mt][nt][half * 2 + 1] + bc[nt][1];
                if (MODE == 0) {
                    __half2 h2 = __floats2half2_rn(v0, v1);
                    *reinterpret_cast<uint32_t*>(g_h1 + ((size_t)(gB * MTOK + mrow) * INTER + col)) =
                        *reinterpret_cast<uint32_t*>(&h2);
                } else {
                    *reinterpret_cast<float2*>(outp + ((size_t)gB * MTOK + mrow) * N + col) =
                        make_float2(v0, v1);
                }
            }
        }
    }
}

// ------------------------------ launch ---------------------------------
extern "C" void kernel_launch(void* const* d_in, const int* in_sizes, int n_in,
                              void* d_out, int out_size) {
    const float *x = nullptr, *W1 = nullptr, *b1 = nullptr, *W2 = nullptr, *b2 = nullptr;
    for (int i = 0; i < n_in; i++) {
        const int s = in_sizes[i];
        if (s == GROUPS * MTOK * HID)        x = (const float*)d_in[i];
        else if (s == GROUPS * INTER * HID) { if (!W1) W1 = (const float*)d_in[i];
                                              else      W2 = (const float*)d_in[i]; }
        else if (s == GROUPS * INTER)        b1 = (const float*)d_in[i];
        else if (s == GROUPS * HID)          b2 = (const float*)d_in[i];
    }

    cudaFuncSetAttribute(gemm_kernel<0>, cudaFuncAttributeMaxDynamicSharedMemorySize, SMEM_DYN);
    cudaFuncSetAttribute(gemm_kernel<1>, cudaFuncAttributeMaxDynamicSharedMemorySize, SMEM_DYN);

    // 1) prep: fp32 -> fp16 converts
    {
        int n4x = GROUPS * MTOK * HID / 4;
        conv_kernel<0><<<(n4x + 255) / 256, 256>>>((const float4*)x, n4x);
        int n4w = GROUPS * INTER * HID / 4;
        conv_kernel<1><<<(n4w + 255) / 256, 256>>>((const float4*)W1, n4w);
        conv_kernel<2><<<(n4w + 255) / 256, 256>>>((const float4*)W2, n4w);
    }

    // 2) GEMM1: h1 = x @ W1^T + b1  (M=2048, N=4096, K=1024 per group)
    {
        dim3 grid(INTER / 256, MTOK / 128, GROUPS);
        gemm_kernel<0><<<grid, 256, SMEM_DYN>>>(b1, nullptr);
    }

    // 3) GEMM2: out = h1 @ W2^T + b2 (M=2048, N=1024, K=4096 per group)
    {
        dim3 grid(HID / 256, MTOK / 128, GROUPS);
        gemm_kernel<1><<<grid, 256, SMEM_DYN>>>(b2, (float*)d_out);
    }
}

// round 16
// speedup vs baseline: 3.1981x; 1.0022x over previous
#include <cuda_runtime.h>
#include <cuda_fp16.h>
#include <cstdint>

#define DI __device__ __forceinline__

static constexpr int GROUPS = 8, MTOK = 2048, HID = 1024, INTER = 4096;

// ---------------------------------------------------------------------------
// Single-term fp16 scheme: all operands plain row-major fp16, fp32 accumulate.
//   GEMM1: h1 = x @ W1^T + b1   (fp16 h1)   tile 128x256
//   GEMM2: out = h1 @ W2^T + b2 (fp32 out)  tile 128x128 (wave quantization)
// Calibrated: ~2.1e-4 rel err per fp16 quant event; 4 events -> ~4e-4.
// ---------------------------------------------------------------------------

__device__ __half g_x [(size_t)GROUPS * MTOK * HID];
__device__ __half g_w1[(size_t)GROUPS * INTER * HID];
__device__ __half g_w2[(size_t)GROUPS * HID * INTER];
__device__ __half g_h1[(size_t)GROUPS * MTOK * INTER];

// ------------------------------ helpers ------------------------------------
DI uint32_t smem_u32(const void* p) {
    uint32_t a;
    asm("{ .reg .u64 t; cvta.to.shared.u64 t, %1; cvt.u32.u64 %0, t; }" : "=r"(a) : "l"(p));
    return a;
}
DI uint32_t swz(uint32_t off) { return off ^ ((off >> 3) & 0x70); }

DI void cp16(uint32_t s, const void* g) {
    asm volatile("cp.async.cg.shared.global [%0], [%1], 16;"
                 :: "r"(s), "l"(__cvta_generic_to_global(g)) : "memory");
}
DI void cp_commit() { asm volatile("cp.async.commit_group;" ::: "memory"); }

DI void ldm4(uint32_t* r, uint32_t addr) {
    asm volatile("ldmatrix.sync.aligned.m8n8.x4.shared.b16 {%0,%1,%2,%3}, [%4];"
                 : "=r"(r[0]), "=r"(r[1]), "=r"(r[2]), "=r"(r[3]) : "r"(addr));
}
DI void mma_f16(float* d, const uint32_t* a, const uint32_t* b) {
    asm volatile(
        "mma.sync.aligned.m16n8k16.row.col.f32.f16.f16.f32 "
        "{%0,%1,%2,%3}, {%4,%5,%6,%7}, {%8,%9}, {%0,%1,%2,%3};"
        : "+f"(d[0]), "+f"(d[1]), "+f"(d[2]), "+f"(d[3])
        : "r"(a[0]), "r"(a[1]), "r"(a[2]), "r"(a[3]), "r"(b[0]), "r"(b[1]));
}

// ------------------------------ prep kernel ---------------------------------
template <int T>  // 0 -> x, 1 -> W1, 2 -> W2
__global__ void conv_kernel(const float4* __restrict__ src, int n4) {
    __half* dst = (T == 0) ? g_x : ((T == 1) ? g_w1 : g_w2);
    int i = blockIdx.x * 256 + threadIdx.x;
    if (i >= n4) return;
    float4 v = src[i];
    __half2 h01 = __floats2half2_rn(v.x, v.y);
    __half2 h23 = __floats2half2_rn(v.z, v.w);
    *reinterpret_cast<uint2*>(dst + (size_t)i * 4) =
        make_uint2(*reinterpret_cast<uint32_t*>(&h01), *reinterpret_cast<uint32_t*>(&h23));
}

// ------------------------------ GEMM kernel ---------------------------------
// CTA tile 128(M) x TN(N), BK = 64 per stage, 4 stages.
// 8 warps: wm = w&1 (M 64 each), wn = w>>1 (N TN/4 each).
// Register double-buffered ldmatrix fragments to overlap LDSM with HMMA.
static constexpr int NSTAGE = 4;

template <int MODE>
__global__ __launch_bounds__(256, 1) void gemm_kernel(const float* __restrict__ bias,
                                                      float* __restrict__ outp) {
    constexpr int K = (MODE == 0) ? HID : INTER;
    constexpr int N = (MODE == 0) ? INTER : HID;
    constexpr int TN = (MODE == 0) ? 256 : 128;
    constexpr int NT = TN / 32;             // n-tiles (of 8) per warp: 8 or 4
    constexpr int NT2 = NT / 2;             // B ldm4 per k16: 4 or 2
    constexpr int NST = K / 64;
    constexpr uint32_t STG = 16384u + (uint32_t)TN * 128u;  // stage bytes
    constexpr long STRIDE = (long)K * 2;

    const int gB = blockIdx.z;
    const int mbase = blockIdx.y * 128;
    const int nbase = blockIdx.x * TN;
    const int t = threadIdx.x;
    const int lane = t & 31, w = t >> 5;
    const int wm = w & 1, wn = w >> 1;

    const char* Abase = reinterpret_cast<const char*>((MODE == 0) ? g_x : g_h1)
                      + ((size_t)gB * MTOK + mbase) * STRIDE;
    const char* Bbase = reinterpret_cast<const char*>((MODE == 0) ? g_w1 : g_w2)
                      + ((size_t)gB * N + nbase) * STRIDE;

    extern __shared__ char smem[];
    const uint32_t sb = smem_u32(smem);

    // ldmatrix lane offsets
    const int rowA = (lane & 7) + ((lane >> 3) & 1) * 8;
    const int kA   = (lane >> 4) * 8;
    const int rowB = (lane & 7) + ((lane >> 4) & 1) * 8;
    const int kB   = ((lane >> 3) & 1) * 8;
    const uint32_t offA = (uint32_t)((wm * 64 + rowA) * 128 + kA * 2);
    const uint32_t offB = (uint32_t)((wn * (TN / 4) + rowB) * 128 + kB * 2);

    float d[4][NT][4];
    #pragma unroll
    for (int a = 0; a < 4; a++)
        #pragma unroll
        for (int b = 0; b < NT; b++)
            #pragma unroll
            for (int c = 0; c < 4; c++) d[a][b][c] = 0.f;

    auto load_stage = [&](int s) {
        const uint32_t dst = sb + (uint32_t)(s % NSTAGE) * STG;
        const char* As = Abase + (size_t)s * 128;
        #pragma unroll
        for (int i = 0; i < 4; i++) {                  // A: 1024 chunks
            int q = t + 256 * i;
            int row = q >> 3, cb = (q & 7) * 16;
            cp16(dst + swz((uint32_t)(row * 128 + cb)), As + (size_t)row * STRIDE + cb);
        }
        const char* Bs = Bbase + (size_t)s * 128;
        #pragma unroll
        for (int i = 0; i < TN / 32; i++) {            // B: TN*8 chunks
            int q = t + 256 * i;
            int row = q >> 3, cb = (q & 7) * 16;
            cp16(dst + 16384 + swz((uint32_t)(row * 128 + cb)), Bs + (size_t)row * STRIDE + cb);
        }
        cp_commit();
    };

    #pragma unroll
    for (int s = 0; s < NSTAGE - 1; s++) load_stage(s);

    uint32_t a4[2][4][4], b4[2][NT2][4];

    for (int ks = 0; ks < NST; ks++) {
        asm volatile("cp.async.wait_group 2;" ::: "memory");
        __syncthreads();

        const uint32_t ab = sb + (uint32_t)(ks % NSTAGE) * STG;
        const uint32_t bb = ab + 16384;

        // prefetch ki=0 fragments first, then kick off the next stage's loads
        #pragma unroll
        for (int mt = 0; mt < 4; mt++)
            ldm4(a4[0][mt], ab + swz(offA + (uint32_t)(mt * 2048)));
        #pragma unroll
        for (int np = 0; np < NT2; np++)
            ldm4(b4[0][np], bb + swz(offB + (uint32_t)(np * 2048)));

        if (ks + NSTAGE - 1 < NST) load_stage(ks + NSTAGE - 1);
        else cp_commit();

        #pragma unroll
        for (int ki = 0; ki < 4; ki++) {
            const int cur = ki & 1, nxt = cur ^ 1;
            if (ki < 3) {
                const uint32_t ko = (uint32_t)((ki + 1) * 32);
                #pragma unroll
                for (int mt = 0; mt < 4; mt++)
                    ldm4(a4[nxt][mt], ab + swz(offA + (uint32_t)(mt * 2048) + ko));
                #pragma unroll
                for (int np = 0; np < NT2; np++)
                    ldm4(b4[nxt][np], bb + swz(offB + (uint32_t)(np * 2048) + ko));
            }
            #pragma unroll
            for (int mt = 0; mt < 4; mt++)
                #pragma unroll
                for (int nt = 0; nt < NT; nt++)
                    mma_f16(d[mt][nt], a4[cur][mt], &b4[cur][nt >> 1][(nt & 1) * 2]);
        }
    }

    // ------------------------------ epilogue --------------------------------
    const int g = lane >> 2, tg = lane & 3;
    const float* bs = bias + (size_t)gB * N;
    float bc[NT][2];
    #pragma unroll
    for (int nt = 0; nt < NT; nt++) {
        const int col = nbase + wn * (TN / 4) + nt * 8 + 2 * tg;
        bc[nt][0] = bs[col];
        bc[nt][1] = bs[col + 1];
    }
    #pragma unroll
    for (int mt = 0; mt < 4; mt++) {
        #pragma unroll
        for (int half = 0; half < 2; half++) {
            const int mrow = mbase + wm * 64 + mt * 16 + g + half * 8;
            #pragma unroll
            for (int nt = 0; nt < NT; nt++) {
                const int col = nbase + wn * (TN / 4) + nt * 8 + 2 * tg;
                float v0 = d[mt][nt][half * 2 + 0] + bc[nt][0];
                float v1 = d[mt][nt][half * 2 + 1] + bc[nt][1];
                if (MODE == 0) {
                    __half2 h2 = __floats2half2_rn(v0, v1);
                    *reinterpret_cast<uint32_t*>(g_h1 + ((size_t)(gB * MTOK + mrow) * INTER + col)) =
                        *reinterpret_cast<uint32_t*>(&h2);
                } else {
                    *reinterpret_cast<float2*>(outp + ((size_t)gB * MTOK + mrow) * N + col) =
                        make_float2(v0, v1);
                }
            }
        }
    }
}

// ------------------------------ launch ---------------------------------
extern "C" void kernel_launch(void* const* d_in, const int* in_sizes, int n_in,
                              void* d_out, int out_size) {
    const float *x = nullptr, *W1 = nullptr, *b1 = nullptr, *W2 = nullptr, *b2 = nullptr;
    for (int i = 0; i < n_in; i++) {
        const int s = in_sizes[i];
        if (s == GROUPS * MTOK * HID)        x = (const float*)d_in[i];
        else if (s == GROUPS * INTER * HID) { if (!W1) W1 = (const float*)d_in[i];
                                              else      W2 = (const float*)d_in[i]; }
        else if (s == GROUPS * INTER)        b1 = (const float*)d_in[i];
        else if (s == GROUPS * HID)          b2 = (const float*)d_in[i];
    }

    constexpr uint32_t SMEM1 = NSTAGE * (16384u + 256u * 128u);  // 196608
    constexpr uint32_t SMEM2 = NSTAGE * (16384u + 128u * 128u);  // 131072
    cudaFuncSetAttribute(gemm_kernel<0>, cudaFuncAttributeMaxDynamicSharedMemorySize, SMEM1);
    cudaFuncSetAttribute(gemm_kernel<1>, cudaFuncAttributeMaxDynamicSharedMemorySize, SMEM2);

    // 1) prep: fp32 -> fp16 converts
    {
        int n4x = GROUPS * MTOK * HID / 4;
        conv_kernel<0><<<(n4x + 255) / 256, 256>>>((const float4*)x, n4x);
        int n4w = GROUPS * INTER * HID / 4;
        conv_kernel<1><<<(n4w + 255) / 256, 256>>>((const float4*)W1, n4w);
        conv_kernel<2><<<(n4w + 255) / 256, 256>>>((const float4*)W2, n4w);
    }

    // 2) GEMM1: h1 = x @ W1^T + b1  (tile 128x256)
    {
        dim3 grid(INTER / 256, MTOK / 128, GROUPS);
        gemm_kernel<0><<<grid, 256, SMEM1>>>(b1, nullptr);
    }

    // 3) GEMM2: out = h1 @ W2^T + b2 (tile 128x128)
    {
        dim3 grid(HID / 128, MTOK / 128, GROUPS);
        gemm_kernel<1><<<grid, 256, SMEM2>>>(b2, (float*)d_out);
    }
}

// round 17
// speedup vs baseline: 3.6349x; 1.1366x over previous
#include <cuda_runtime.h>
#include <cuda_fp16.h>
#include <cstdint>

#define DI __device__ __forceinline__

static constexpr int GROUPS = 8, MTOK = 2048, HID = 1024, INTER = 4096;

// ---------------------------------------------------------------------------
// Single-term fp16 scheme, 2 CTAs/SM:
//   GEMM1: h1 = x @ W1^T + b1   (fp16 h1)
//   GEMM2: out = h1 @ W2^T + b2 (fp32 out)
// CTA tile 128x128, BK=64, 3 stages x 32KB = 96KB smem, 256 thr, <=128 regs.
// ---------------------------------------------------------------------------

__device__ __half g_x [(size_t)GROUPS * MTOK * HID];
__device__ __half g_w1[(size_t)GROUPS * INTER * HID];
__device__ __half g_w2[(size_t)GROUPS * HID * INTER];
__device__ __half g_h1[(size_t)GROUPS * MTOK * INTER];

// ------------------------------ helpers ------------------------------------
DI uint32_t smem_u32(const void* p) {
    uint32_t a;
    asm("{ .reg .u64 t; cvta.to.shared.u64 t, %1; cvt.u32.u64 %0, t; }" : "=r"(a) : "l"(p));
    return a;
}
DI uint32_t swz(uint32_t off) { return off ^ ((off >> 3) & 0x70); }

DI void cp16(uint32_t s, const void* g) {
    asm volatile("cp.async.cg.shared.global [%0], [%1], 16;"
                 :: "r"(s), "l"(__cvta_generic_to_global(g)) : "memory");
}
DI void cp_commit() { asm volatile("cp.async.commit_group;" ::: "memory"); }

DI void ldm4(uint32_t* r, uint32_t addr) {
    asm volatile("ldmatrix.sync.aligned.m8n8.x4.shared.b16 {%0,%1,%2,%3}, [%4];"
                 : "=r"(r[0]), "=r"(r[1]), "=r"(r[2]), "=r"(r[3]) : "r"(addr));
}
DI void mma_f16(float* d, const uint32_t* a, const uint32_t* b) {
    asm volatile(
        "mma.sync.aligned.m16n8k16.row.col.f32.f16.f16.f32 "
        "{%0,%1,%2,%3}, {%4,%5,%6,%7}, {%8,%9}, {%0,%1,%2,%3};"
        : "+f"(d[0]), "+f"(d[1]), "+f"(d[2]), "+f"(d[3])
        : "r"(a[0]), "r"(a[1]), "r"(a[2]), "r"(a[3]), "r"(b[0]), "r"(b[1]));
}

// ------------------------------ prep kernel ---------------------------------
template <int T>  // 0 -> x, 1 -> W1, 2 -> W2
__global__ void conv_kernel(const float4* __restrict__ src, int n4) {
    __half* dst = (T == 0) ? g_x : ((T == 1) ? g_w1 : g_w2);
    int i = blockIdx.x * 256 + threadIdx.x;
    if (i >= n4) return;
    float4 v = src[i];
    __half2 h01 = __floats2half2_rn(v.x, v.y);
    __half2 h23 = __floats2half2_rn(v.z, v.w);
    *reinterpret_cast<uint2*>(dst + (size_t)i * 4) =
        make_uint2(*reinterpret_cast<uint32_t*>(&h01), *reinterpret_cast<uint32_t*>(&h23));
}

// ------------------------------ GEMM kernel ---------------------------------
// CTA tile 128(M) x 128(N), BK = 64 per stage, 3 stages, 2 CTAs/SM.
// 8 warps: wm = w&1 (64 M-rows), wn = w>>1 (32 N-rows). Warp tile 64x32.
static constexpr int NSTAGE = 3;
static constexpr uint32_t STG = 32768;
static constexpr uint32_t SMEM_DYN = NSTAGE * STG;  // 98304

template <int MODE>
__global__ __launch_bounds__(256, 2) void gemm_kernel(const float* __restrict__ bias,
                                                      float* __restrict__ outp) {
    constexpr int K = (MODE == 0) ? HID : INTER;
    constexpr int N = (MODE == 0) ? INTER : HID;
    constexpr int NST = K / 64;
    constexpr long STRIDE = (long)K * 2;

    const int gB = blockIdx.z;
    const int mbase = blockIdx.y * 128;
    const int nbase = blockIdx.x * 128;
    const int t = threadIdx.x;
    const int lane = t & 31, w = t >> 5;
    const int wm = w & 1, wn = w >> 1;

    const char* Abase = reinterpret_cast<const char*>((MODE == 0) ? g_x : g_h1)
                      + ((size_t)gB * MTOK + mbase) * STRIDE;
    const char* Bbase = reinterpret_cast<const char*>((MODE == 0) ? g_w1 : g_w2)
                      + ((size_t)gB * N + nbase) * STRIDE;

    extern __shared__ char smem[];
    const uint32_t sb = smem_u32(smem);

    // ldmatrix lane offsets
    const int rowA = (lane & 7) + ((lane >> 3) & 1) * 8;
    const int kA   = (lane >> 4) * 8;
    const int rowB = (lane & 7) + ((lane >> 4) & 1) * 8;
    const int kB   = ((lane >> 3) & 1) * 8;
    const uint32_t offA = (uint32_t)((wm * 64 + rowA) * 128 + kA * 2);
    const uint32_t offB = (uint32_t)((wn * 32 + rowB) * 128 + kB * 2);

    float d[4][4][4];
    #pragma unroll
    for (int a = 0; a < 4; a++)
        #pragma unroll
        for (int b = 0; b < 4; b++)
            #pragma unroll
            for (int c = 0; c < 4; c++) d[a][b][c] = 0.f;

    auto load_stage = [&](int s) {
        const uint32_t dst = sb + (uint32_t)(s % NSTAGE) * STG;
        const char* As = Abase + (size_t)s * 128;
        const char* Bs = Bbase + (size_t)s * 128;
        #pragma unroll
        for (int i = 0; i < 4; i++) {   // A: 1024 chunks, B: 1024 chunks
            int q = t + 256 * i;
            int row = q >> 3, cb = (q & 7) * 16;
            uint32_t so = swz((uint32_t)(row * 128 + cb));
            cp16(dst + so,          As + (size_t)row * STRIDE + cb);
            cp16(dst + 16384u + so, Bs + (size_t)row * STRIDE + cb);
        }
        cp_commit();
    };

    #pragma unroll
    for (int s = 0; s < NSTAGE - 1; s++) load_stage(s);

    for (int ks = 0; ks < NST; ks++) {
        asm volatile("cp.async.wait_group 1;" ::: "memory");
        __syncthreads();
        if (ks + NSTAGE - 1 < NST) load_stage(ks + NSTAGE - 1);
        else cp_commit();

        const uint32_t ab = sb + (uint32_t)(ks % NSTAGE) * STG;
        const uint32_t bb = ab + 16384u;

        #pragma unroll
        for (int ki = 0; ki < 4; ki++) {
            uint32_t a4[4][4], b4[2][4];
            const uint32_t ko = (uint32_t)(ki * 32);
            #pragma unroll
            for (int mt = 0; mt < 4; mt++)
                ldm4(a4[mt], ab + swz(offA + (uint32_t)(mt * 2048) + ko));
            #pragma unroll
            for (int np = 0; np < 2; np++)
                ldm4(b4[np], bb + swz(offB + (uint32_t)(np * 2048) + ko));
            #pragma unroll
            for (int mt = 0; mt < 4; mt++)
                #pragma unroll
                for (int nt = 0; nt < 4; nt++)
                    mma_f16(d[mt][nt], a4[mt], &b4[nt >> 1][(nt & 1) * 2]);
        }
    }

    // ------------------------------ epilogue --------------------------------
    const int g = lane >> 2, tg = lane & 3;
    const float* bs = bias + (size_t)gB * N;
    #pragma unroll
    for (int mt = 0; mt < 4; mt++) {
        #pragma unroll
        for (int half = 0; half < 2; half++) {
            const int mrow = mbase + wm * 64 + mt * 16 + g + half * 8;
            #pragma unroll
            for (int nt = 0; nt < 4; nt++) {
                const int col = nbase + wn * 32 + nt * 8 + 2 * tg;
                float v0 = d[mt][nt][half * 2 + 0] + bs[col];
                float v1 = d[mt][nt][half * 2 + 1] + bs[col + 1];
                if (MODE == 0) {
                    __half2 h2 = __floats2half2_rn(v0, v1);
                    *reinterpret_cast<uint32_t*>(g_h1 + ((size_t)(gB * MTOK + mrow) * INTER + col)) =
                        *reinterpret_cast<uint32_t*>(&h2);
                } else {
                    *reinterpret_cast<float2*>(outp + ((size_t)gB * MTOK + mrow) * N + col) =
                        make_float2(v0, v1);
                }
            }
        }
    }
}

// ------------------------------ launch ---------------------------------
extern "C" void kernel_launch(void* const* d_in, const int* in_sizes, int n_in,
                              void* d_out, int out_size) {
    const float *x = nullptr, *W1 = nullptr, *b1 = nullptr, *W2 = nullptr, *b2 = nullptr;
    for (int i = 0; i < n_in; i++) {
        const int s = in_sizes[i];
        if (s == GROUPS * MTOK * HID)        x = (const float*)d_in[i];
        else if (s == GROUPS * INTER * HID) { if (!W1) W1 = (const float*)d_in[i];
                                              else      W2 = (const float*)d_in[i]; }
        else if (s == GROUPS * INTER)        b1 = (const float*)d_in[i];
        else if (s == GROUPS * HID)          b2 = (const float*)d_in[i];
    }

    cudaFuncSetAttribute(gemm_kernel<0>, cudaFuncAttributeMaxDynamicSharedMemorySize, SMEM_DYN);
    cudaFuncSetAttribute(gemm_kernel<1>, cudaFuncAttributeMaxDynamicSharedMemorySize, SMEM_DYN);

    // 1) prep: fp32 -> fp16 converts
    {
        int n4x = GROUPS * MTOK * HID / 4;
        conv_kernel<0><<<(n4x + 255) / 256, 256>>>((const float4*)x, n4x);
        int n4w = GROUPS * INTER * HID / 4;
        conv_kernel<1><<<(n4w + 255) / 256, 256>>>((const float4*)W1, n4w);
        conv_kernel<2><<<(n4w + 255) / 256, 256>>>((const float4*)W2, n4w);
    }

    // 2) GEMM1: h1 = x @ W1^T + b1  (M=2048, N=4096, K=1024 per group)
    {
        dim3 grid(INTER / 128, MTOK / 128, GROUPS);
        gemm_kernel<0><<<grid, 256, SMEM_DYN>>>(b1, nullptr);
    }

    // 3) GEMM2: out = h1 @ W2^T + b2 (M=2048, N=1024, K=4096 per group)
    {
        dim3 grid(HID / 128, MTOK / 128, GROUPS);
        gemm_kernel<1><<<grid, 256, SMEM_DYN>>>(b2, (float*)d_out);
    }
}